// round 9
// baseline (speedup 1.0000x reference)
#include <cuda_runtime.h>
#include <cuda_bf16.h>
#include <cstddef>

// Shapes: user [B=32, U=128, D=256] fp32, image [B=32, I=256, D=256] fp32
// out = concat(user * img_sum[b,1,:], image * user_sum[b,1,:])
//
// Single-wave config: grid = 32 batches x 4 d-chunks(64 floats) = 128 CTAs
// (<=148 SMs, ONE wave, no wave transition), 512 threads. R5's proven
// structure otherwise: all 12 input rows per thread loaded up front into
// registers, both sums via one shuffle tree + one smem round + ONE barrier,
// all stores from registers. Traffic = 24MB minimum.

#define BB 32
#define UU 128
#define II 256
#define DD 256

#define TX 16                // float4 lanes: 64 floats = 256B per warp row
#define TY 32                // row groups
#define NT (TX * TY)         // 512 threads
#define DCH 64               // d-chunk per CTA
#define NCH (DD / DCH)       // 4
#define GRID (BB * NCH)      // 128 -> single wave
#define NWARPS (NT / 32)     // 16

__device__ __forceinline__ float4 f4add(float4 a, float4 b) {
    return make_float4(a.x + b.x, a.y + b.y, a.z + b.z, a.w + b.w);
}
__device__ __forceinline__ float4 f4mul(float4 a, float4 b) {
    return make_float4(a.x * b.x, a.y * b.y, a.z * b.z, a.w * b.w);
}
__device__ __forceinline__ void f4shfl_acc(float4& a, int m) {
    a.x += __shfl_xor_sync(0xffffffffu, a.x, m);
    a.y += __shfl_xor_sync(0xffffffffu, a.y, m);
    a.z += __shfl_xor_sync(0xffffffffu, a.z, m);
    a.w += __shfl_xor_sync(0xffffffffu, a.w, m);
}

__global__ __launch_bounds__(NT, 1)
void ExternalInteraction_65609920413984_kernel(
    const float* __restrict__ user,
    const float* __restrict__ img,
    float* __restrict__ out_user,
    float* __restrict__ out_img)
{
    __shared__ float4 wsI[NWARPS][TX / 2];   // each warp covers 2 ty-rows of 16 lanes
    __shared__ float4 wsU[NWARPS][TX / 2];

    const int b  = blockIdx.x >> 2;               // / NCH
    const int d0 = (blockIdx.x & (NCH - 1)) * DCH;
    const int tx = threadIdx.x & (TX - 1);        // 0..15
    const int ty = threadIdx.x >> 4;              // 0..31
    const int warp = threadIdx.x >> 5;
    const int lane = threadIdx.x & 31;
    const int d  = d0 + tx * 4;
    const int rs = DD / 4;                        // row stride in float4

    const float4* up = reinterpret_cast<const float4*>(user + (size_t)b * UU * DD + d);
    const float4* ip = reinterpret_cast<const float4*>(img  + (size_t)b * II * DD + d);
    float4* ou = reinterpret_cast<float4*>(out_user + (size_t)b * UU * DD + d);
    float4* oi = reinterpret_cast<float4*>(out_img  + (size_t)b * II * DD + d);

    // ---- Phase A: all loads up front (12 independent float4 / thread) ----
    float4 iv[II / TY];   // 8
    float4 uv[UU / TY];   // 4
    #pragma unroll
    for (int k = 0; k < II / TY; k++)
        iv[k] = ip[(size_t)(ty + k * TY) * rs];
    #pragma unroll
    for (int k = 0; k < UU / TY; k++)
        uv[k] = up[(size_t)(ty + k * TY) * rs];

    // ---- Phase B: both column sums ----
    float4 ai = f4add(f4add(f4add(iv[0], iv[1]), f4add(iv[2], iv[3])),
                      f4add(f4add(iv[4], iv[5]), f4add(iv[6], iv[7])));
    float4 au = f4add(f4add(uv[0], uv[1]), f4add(uv[2], uv[3]));

    // Each warp holds 2 ty-rows (ty bit 0 = lane bit 4). Fold them: xor 16.
    f4shfl_acc(ai, 16);
    f4shfl_acc(au, 16);

    // lanes 0..15 hold the warp partial for their tx... but note after xor16
    // every lane has the 2-row partial for its own tx, so lanes 0..15 cover
    // tx 0..15. Warp w covers ty = {2w, 2w+1}. Stash 8 float4 per warp? No:
    // 16 lanes x float4 = wsI[w][0..15] -> but we declared TX/2=8. Fix: use
    // lanes 0..15 writing 16 slots requires [NWARPS][16]; we fold pairs of
    // warps later instead. Simplest correct: store all 16 lanes.
    // (see wsI2/wsU2 below)
    __shared__ float4 wsI2[NWARPS][TX];
    __shared__ float4 wsU2[NWARPS][TX];
    if (lane < TX) { wsI2[warp][lane] = ai; wsU2[warp][lane] = au; }
    __syncthreads();                       // the ONLY barrier

    float4 is = wsI2[0][tx];
    float4 us = wsU2[0][tx];
    #pragma unroll
    for (int w = 1; w < NWARPS; w++) {
        is = f4add(is, wsI2[w][tx]);
        us = f4add(us, wsU2[w][tx]);
    }

    // ---- Phase C: stores from registers ----
    #pragma unroll
    for (int k = 0; k < UU / TY; k++)
        ou[(size_t)(ty + k * TY) * rs] = f4mul(uv[k], is);
    #pragma unroll
    for (int k = 0; k < II / TY; k++)
        oi[(size_t)(ty + k * TY) * rs] = f4mul(iv[k], us);

    (void)wsI; (void)wsU;
}

extern "C" void kernel_launch(void* const* d_in, const int* in_sizes, int n_in,
                              void* d_out, int out_size)
{
    (void)in_sizes; (void)n_in; (void)out_size;
    const float* user = (const float*)d_in[0];
    const float* img  = (const float*)d_in[1];
    float* out_user = (float*)d_out;
    float* out_img  = (float*)d_out + (size_t)BB * UU * DD;

    ExternalInteraction_65609920413984_kernel
        <<<GRID, NT>>>(user, img, out_user, out_img);
}